// round 2
// baseline (speedup 1.0000x reference)
#include <cuda_runtime.h>
#include <math.h>

#define BATCH   8
#define SEQ     200
#define NNODES  512
#define HID     64
#define NEDGES  2048
#define ALPHA   0.2f
#define NEGBIG  -9.0e15f

// ---------------- scratch (device globals, no allocation) ----------------
__device__ float g_h0[BATCH * NNODES * HID];
__device__ float g_Wh[BATCH * NNODES * HID];
__device__ float g_h1[BATCH * NNODES * HID];
__device__ float g_h2[BATCH * NNODES * HID];
__device__ float g_f1[BATCH * NNODES];
__device__ float g_f2[BATCH * NNODES];

// ---------------- packed fp32x2 helpers (sm_103a FFMA2 path) ----------------
__device__ __forceinline__ void fma2(unsigned long long& d,
                                     unsigned long long a,
                                     unsigned long long b) {
    asm("fma.rn.f32x2 %0, %1, %2, %0;" : "+l"(d) : "l"(a), "l"(b));
}
__device__ __forceinline__ void unpack2(float& lo, float& hi, unsigned long long v) {
    asm("mov.b64 {%0, %1}, %2;" : "=f"(lo), "=f"(hi) : "l"(v));
}

// ---------------- Stage A: fused conv1+relu+conv2+relu+mean ----------------
// One block per (b, n). 256 threads.
// smem layout (floats):
//   s_in   [2][208]                         (padded input)
//   s_h1d  [32][208] of float2 (h,h)        (conv1 out, pre-broadcast for FFMA2)
//   s_w2p  [160][32] of float2 (w_oc0,w_oc1) (conv2 weights, channel-paired)
//   s_w1   [320]
//   s_red  [64][8]
#define S_IN_OFF    0
#define S_H1D_OFF   (2 * 208)                      // float2 units counted as 2 floats
#define S_W2_OFF    (S_H1D_OFF + 32 * 208 * 2)
#define S_W1_OFF    (S_W2_OFF + 160 * 32 * 2)
#define S_RED_OFF   (S_W1_OFF + 320)
#define CONV_SMEM_FLOATS (S_RED_OFF + 64 * 8)
#define CONV_SMEM_BYTES  (CONV_SMEM_FLOATS * 4)

__global__ void __launch_bounds__(256, 2)
conv_fused_kernel(const float* __restrict__ x,
                  const float* __restrict__ w1, const float* __restrict__ b1,
                  const float* __restrict__ w2, const float* __restrict__ b2,
                  float* __restrict__ h0)
{
    extern __shared__ float sm[];
    float*              s_in  = sm + S_IN_OFF;
    unsigned long long* s_h1d = (unsigned long long*)(sm + S_H1D_OFF);
    unsigned long long* s_w2p = (unsigned long long*)(sm + S_W2_OFF);
    float*              s_w1  = sm + S_W1_OFF;
    float*              s_red = sm + S_RED_OFF;

    const int bn  = blockIdx.x;
    const int b   = bn >> 9;
    const int n   = bn & 511;
    const int tid = threadIdx.x;

    // zero padded regions
    for (int i = tid; i < 2 * 208; i += 256)  s_in[i] = 0.f;
    for (int i = tid; i < 32 * 208; i += 256) s_h1d[i] = 0ULL;

    // load weights: w1 flat; w2 repacked as channel-pair float2
    for (int i = tid; i < 320; i += 256) s_w1[i] = w1[i];
    for (int i = tid; i < 160 * 32; i += 256) {
        int r   = i >> 5;          // r = ic*5 + k
        int ocg = i & 31;
        float wa = w2[(2 * ocg) * 160 + r];
        float wb = w2[(2 * ocg + 1) * 160 + r];
        ((float2*)s_w2p)[i] = make_float2(wa, wb);
    }

    // load input: xf[bn][c][s] = x[b, s, 2n + c]
    const float* xb = x + (size_t)b * SEQ * (NNODES * 2) + 2 * n;
    __syncthreads();
    for (int i = tid; i < 2 * SEQ; i += 256) {
        int s = i >> 1, c = i & 1;
        s_in[c * 208 + 2 + s] = xb[(size_t)s * (NNODES * 2) + c];
    }
    __syncthreads();

    // conv1: 32 oc x 200 pos, kernel 5, 2 in channels -> write (h,h) pairs
    for (int i = tid; i < 32 * SEQ; i += 256) {
        int oc = i / SEQ, s = i - oc * SEQ;
        const float* w  = s_w1 + oc * 10;
        const float* i0 = s_in + s;
        const float* i1 = s_in + 208 + s;
        float acc = b1[oc];
#pragma unroll
        for (int k = 0; k < 5; k++)
            acc = fmaf(w[k], i0[k], fmaf(w[5 + k], i1[k], acc));
        float v = fmaxf(acc, 0.f);
        ((float2*)s_h1d)[oc * 208 + 2 + s] = make_float2(v, v);
    }
    __syncthreads();

    // conv2 via packed FFMA2: thread = (ocg, sg)
    //   oc pair = (2*ocg, 2*ocg+1) packed in f32x2 lanes; positions [25*sg, 25*sg+25)
    const int ocg = tid & 31;
    const int sg  = tid >> 5;
    const int s0  = sg * 25;

    unsigned long long acc[25];
#pragma unroll
    for (int p = 0; p < 25; p++) acc[p] = 0ULL;

    for (int ic = 0; ic < 32; ic++) {
        const unsigned long long* hrow = s_h1d + ic * 208 + s0;
        unsigned long long wk[5];
#pragma unroll
        for (int k = 0; k < 5; k++) wk[k] = s_w2p[(ic * 5 + k) * 32 + ocg];

        // sub-tile 1: positions 0..12, window h[0..16]
        {
            unsigned long long hp[17];
#pragma unroll
            for (int j = 0; j < 17; j++) hp[j] = hrow[j];
#pragma unroll
            for (int k = 0; k < 5; k++)
#pragma unroll
                for (int p = 0; p < 13; p++)
                    fma2(acc[p], wk[k], hp[p + k]);
        }
        // sub-tile 2: positions 13..24, window h[13..28]
        {
            unsigned long long hp[16];
#pragma unroll
            for (int j = 0; j < 16; j++) hp[j] = hrow[13 + j];
#pragma unroll
            for (int k = 0; k < 5; k++)
#pragma unroll
                for (int p = 0; p < 12; p++)
                    fma2(acc[13 + p], wk[k], hp[p + k]);
        }
    }

    const int oc0 = 2 * ocg;
    const float bias0 = b2[oc0], bias1 = b2[oc0 + 1];
    float sum0 = 0.f, sum1 = 0.f;
#pragma unroll
    for (int p = 0; p < 25; p++) {
        float a0, a1;
        unpack2(a0, a1, acc[p]);
        sum0 += fmaxf(a0 + bias0, 0.f);
        sum1 += fmaxf(a1 + bias1, 0.f);
    }
    s_red[oc0 * 8 + sg]       = sum0;
    s_red[(oc0 + 1) * 8 + sg] = sum1;
    __syncthreads();

    if (tid < 64) {
        float t = 0.f;
#pragma unroll
        for (int r = 0; r < 8; r++) t += s_red[tid * 8 + r];
        h0[(size_t)bn * HID + tid] = t * (1.f / 200.f);
    }
}

// ---------------- Stage B: Wh = h @ W ; f1 = Wh@a[:64] ; f2 = Wh@a[64:] ----
// block = 256 threads, 16 rows per block; grid = 4096/16 = 256
__global__ void __launch_bounds__(256)
gat_pre_kernel(const float* __restrict__ h, const float* __restrict__ W,
               const float* __restrict__ a,
               float* __restrict__ Wh, float* __restrict__ f1, float* __restrict__ f2)
{
    __shared__ float sW[64 * 64];
    __shared__ float sh[16 * 64];
    __shared__ float s1[8][4], s2[8][4];

    const int tid  = threadIdx.x;
    const int row0 = blockIdx.x * 16;

    for (int i = tid; i < 64 * 64; i += 256) sW[i] = W[i];
    for (int i = tid; i < 16 * 64; i += 256) sh[i] = h[(size_t)row0 * 64 + i];
    __syncthreads();

    const int rg = tid >> 6;       // 4 row-groups of 4 rows
    const int d  = tid & 63;
    float acc[4] = {0.f, 0.f, 0.f, 0.f};
#pragma unroll 8
    for (int k = 0; k < 64; k++) {
        float w = sW[k * 64 + d];
#pragma unroll
        for (int j = 0; j < 4; j++)
            acc[j] = fmaf(sh[(rg * 4 + j) * 64 + k], w, acc[j]);
    }
    const float a1v = a[d], a2v = a[64 + d];
    float v1[4], v2[4];
#pragma unroll
    for (int j = 0; j < 4; j++) {
        Wh[(size_t)(row0 + rg * 4 + j) * 64 + d] = acc[j];
        v1[j] = acc[j] * a1v;
        v2[j] = acc[j] * a2v;
    }
#pragma unroll
    for (int o = 16; o; o >>= 1)
#pragma unroll
        for (int j = 0; j < 4; j++) {
            v1[j] += __shfl_down_sync(0xffffffffu, v1[j], o);
            v2[j] += __shfl_down_sync(0xffffffffu, v2[j], o);
        }
    const int w = tid >> 5;
    if ((tid & 31) == 0)
#pragma unroll
        for (int j = 0; j < 4; j++) { s1[w][j] = v1[j]; s2[w][j] = v2[j]; }
    __syncthreads();
    if (tid < 16) {
        int g = tid >> 2, j = tid & 3;      // g = row-group, j = row within group
        f1[row0 + g * 4 + j] = s1[2 * g][j] + s1[2 * g + 1][j];
        f2[row0 + g * 4 + j] = s2[2 * g][j] + s2[2 * g + 1][j];
    }
}

// ---------------- Stage C: attention, 8 rows per block, j-tiled Wh ----------
// grid = 4096/8 = 512, block 256
__global__ void __launch_bounds__(256)
gat_att_kernel(const float* __restrict__ Wh, const float* __restrict__ f1,
               const float* __restrict__ f2, const int* __restrict__ adj,
               float* __restrict__ out, int do_relu)
{
    __shared__ float sp[8][512];      // softmax probs (unnormalized)
    __shared__ float sWh[64][65];     // Wh j-tile, padded
    __shared__ float ssum[8];

    const int blk = blockIdx.x;
    const int b   = blk >> 6;
    const int i0  = (blk & 63) * 8;
    const int tid = threadIdx.x;
    const int w   = tid >> 5;         // warp -> row
    const int ln  = tid & 31;

    // phase A: each warp computes softmax numerators for one row
    {
        const int i  = i0 + w;
        const int bi = b * NNODES + i;
        const float f1i = f1[bi];
        const float* f2b = f2 + b * NNODES;
        const int* adjrow = adj + (size_t)i * NNODES;

        float ev[16];
        float lmax = -3.4e38f;
#pragma unroll
        for (int t = 0; t < 16; t++) {
            int j = ln + t * 32;
            float e = f1i + f2b[j];
            e = (e > 0.f) ? e : ALPHA * e;
            e = (adjrow[j] > 0) ? e : NEGBIG;
            ev[t] = e;
            lmax = fmaxf(lmax, e);
        }
#pragma unroll
        for (int o = 16; o; o >>= 1)
            lmax = fmaxf(lmax, __shfl_xor_sync(0xffffffffu, lmax, o));
        float lsum = 0.f;
#pragma unroll
        for (int t = 0; t < 16; t++) {
            float p = expf(ev[t] - lmax);
            sp[w][ln + t * 32] = p;
            lsum += p;
        }
#pragma unroll
        for (int o = 16; o; o >>= 1)
            lsum += __shfl_xor_sync(0xffffffffu, lsum, o);
        if (ln == 0) ssum[w] = lsum;
    }
    __syncthreads();

    // phase B: acc[i][d] = sum_j p[i][j] * Wh[b][j][d], j tiled by 64
    const int g = tid >> 6;           // 4 groups, 2 rows each
    const int d = tid & 63;
    const float* Whb = Wh + (size_t)b * NNODES * HID;
    float acc0 = 0.f, acc1 = 0.f;

    for (int jt = 0; jt < 8; jt++) {
#pragma unroll
        for (int t = 0; t < 16; t++) {
            int idx = tid + t * 256;
            int j = idx >> 6, dd = idx & 63;
            sWh[j][dd] = Whb[(size_t)(jt * 64 + j) * 64 + dd];
        }
        __syncthreads();
        const float* p0 = &sp[2 * g][jt * 64];
        const float* p1 = &sp[2 * g + 1][jt * 64];
#pragma unroll 8
        for (int j = 0; j < 64; j++) {
            float wv = sWh[j][d];
            acc0 = fmaf(p0[j], wv, acc0);
            acc1 = fmaf(p1[j], wv, acc1);
        }
        __syncthreads();
    }

    {
        float v0 = acc0 / ssum[2 * g];
        float v1 = acc1 / ssum[2 * g + 1];
        if (do_relu) { v0 = fmaxf(v0, 0.f); v1 = fmaxf(v1, 0.f); }
        out[(size_t)(b * NNODES + i0 + 2 * g) * HID + d]     = v0;
        out[(size_t)(b * NNODES + i0 + 2 * g + 1) * HID + d] = v1;
    }
}

// ---------------- Stage D: edge gather + MLP + sigmoid ----------------
// grid (2048, 8), 64 threads
__global__ void __launch_bounds__(64)
edge_mlp_kernel(const float* __restrict__ h, const int* __restrict__ eidx,
                const float* __restrict__ fc1w, const float* __restrict__ fc1b,
                const float* __restrict__ fc2w, const float* __restrict__ fc2b,
                float* __restrict__ out)
{
    __shared__ float she[128];
    __shared__ float sr[2];

    const int e   = blockIdx.x;
    const int b   = blockIdx.y;
    const int tid = threadIdx.x;

    const int i1 = eidx[2 * e];
    const int i2 = eidx[2 * e + 1];
    she[tid]      = h[((size_t)b * NNODES + i1) * HID + tid];
    she[64 + tid] = h[((size_t)b * NNODES + i2) * HID + tid];
    __syncthreads();

    float acc = fc1b[tid];
#pragma unroll 8
    for (int k = 0; k < 128; k++)
        acc = fmaf(she[k], fc1w[(size_t)k * 64 + tid], acc);
    acc = fmaxf(acc, 0.f);

    float v = acc * fc2w[tid];
#pragma unroll
    for (int o = 16; o; o >>= 1)
        v += __shfl_down_sync(0xffffffffu, v, o);
    if ((tid & 31) == 0) sr[tid >> 5] = v;
    __syncthreads();
    if (tid == 0) {
        float z = sr[0] + sr[1] + fc2b[0];
        out[(size_t)b * NEDGES + e] = 1.f / (1.f + expf(-z));
    }
}

// ---------------- launch ----------------
extern "C" void kernel_launch(void* const* d_in, const int* in_sizes, int n_in,
                              void* d_out, int out_size)
{
    const float* x    = (const float*)d_in[0];
    const int*   adj  = (const int*)  d_in[1];
    const int*   eidx = (const int*)  d_in[2];
    const float* w1   = (const float*)d_in[3];
    const float* b1   = (const float*)d_in[4];
    const float* w2   = (const float*)d_in[5];
    const float* b2   = (const float*)d_in[6];
    const float* W1   = (const float*)d_in[7];
    const float* a1   = (const float*)d_in[8];
    const float* W2   = (const float*)d_in[9];
    const float* a2   = (const float*)d_in[10];
    const float* fc1w = (const float*)d_in[11];
    const float* fc1b = (const float*)d_in[12];
    const float* fc2w = (const float*)d_in[13];
    const float* fc2b = (const float*)d_in[14];
    float* out = (float*)d_out;

    float *h0, *Wh, *h1, *h2, *f1, *f2;
    cudaGetSymbolAddress((void**)&h0, g_h0);
    cudaGetSymbolAddress((void**)&Wh, g_Wh);
    cudaGetSymbolAddress((void**)&h1, g_h1);
    cudaGetSymbolAddress((void**)&h2, g_h2);
    cudaGetSymbolAddress((void**)&f1, g_f1);
    cudaGetSymbolAddress((void**)&f2, g_f2);

    cudaFuncSetAttribute(conv_fused_kernel,
                         cudaFuncAttributeMaxDynamicSharedMemorySize,
                         CONV_SMEM_BYTES);

    // Stage A: per-node temporal conv feature extractor (FFMA2 packed)
    conv_fused_kernel<<<BATCH * NNODES, 256, CONV_SMEM_BYTES>>>(x, w1, b1, w2, b2, h0);

    // GAT layer 1 (relu on output)
    gat_pre_kernel<<<(BATCH * NNODES) / 16, 256>>>(h0, W1, a1, Wh, f1, f2);
    gat_att_kernel<<<(BATCH * NNODES) / 8, 256>>>(Wh, f1, f2, adj, h1, 1);

    // GAT layer 2 (no relu)
    gat_pre_kernel<<<(BATCH * NNODES) / 16, 256>>>(h1, W2, a2, Wh, f1, f2);
    gat_att_kernel<<<(BATCH * NNODES) / 8, 256>>>(Wh, f1, f2, adj, h2, 0);

    // Edge MLP
    dim3 eg(NEDGES, BATCH);
    edge_mlp_kernel<<<eg, 64>>>(h2, eidx, fc1w, fc1b, fc2w, fc2b, out);
}

// round 3
// speedup vs baseline: 1.8711x; 1.8711x over previous
#include <cuda_runtime.h>
#include <math.h>
#include <stdint.h>

#define BATCH   8
#define SEQ     200
#define NNODES  512
#define HID     64
#define NEDGES  2048
#define ALPHA   0.2f
#define NEGBIG  -9.0e15f

// ---------------- scratch (device globals, no allocation) ----------------
__device__ float g_h0[BATCH * NNODES * HID];
__device__ float g_Wh[BATCH * NNODES * HID];
__device__ float g_h1[BATCH * NNODES * HID];
__device__ float g_h2[BATCH * NNODES * HID];
__device__ float g_f1[BATCH * NNODES];
__device__ float g_f2[BATCH * NNODES];

// ---------------- tf32 helpers ----------------
__device__ __forceinline__ uint32_t f2tf32(float f) {
    uint32_t r;
    asm("cvt.rna.tf32.f32 %0, %1;" : "=r"(r) : "f"(f));
    return r;
}
__device__ __forceinline__ void mma_tf32(float* c,
                                         uint32_t a0, uint32_t a1, uint32_t a2, uint32_t a3,
                                         uint32_t b0, uint32_t b1) {
    asm volatile(
        "mma.sync.aligned.m16n8k8.row.col.f32.tf32.tf32.f32 "
        "{%0,%1,%2,%3}, {%4,%5,%6,%7}, {%8,%9}, {%0,%1,%2,%3};"
        : "+f"(c[0]), "+f"(c[1]), "+f"(c[2]), "+f"(c[3])
        : "r"(a0), "r"(a1), "r"(a2), "r"(a3), "r"(b0), "r"(b1));
}

// ---------------- Stage A: conv1+relu, then conv2 as tf32 implicit GEMM ----
// One block per (b,n), 256 threads = 8 warps.
// GEMM: M = 256 padded positions (16 m16 tiles, 2 per warp),
//       N = 64 output channels (8 n8 tiles), K = 160 = ic*5+k (20 k8 chunks).
// A[s][r] = h1_tf32[ic][s+k]  (im2col from smem, r = ic*5+k)
// B[r][n] = w2_tf32[n][r]     (smem, row padded to 72 floats -> conflict-free frags)
#define H1W   264
#define W2P   72
#define S_H1_OFF  0
#define S_W2_OFF  (32 * H1W)                  // 8448
#define S_IN_OFF  (S_W2_OFF + 160 * W2P)      // 19968
#define S_W1_OFF  (S_IN_OFF + 2 * 208)        // 20384
#define S_RED_OFF (S_W1_OFF + 320)            // 20704
#define CONV_SMEM_FLOATS (S_RED_OFF + 8 * 64) // 21216
#define CONV_SMEM_BYTES  (CONV_SMEM_FLOATS * 4)

__global__ void __launch_bounds__(256, 2)
conv_fused_kernel(const float* __restrict__ x,
                  const float* __restrict__ w1, const float* __restrict__ b1,
                  const float* __restrict__ w2, const float* __restrict__ b2,
                  float* __restrict__ h0)
{
    extern __shared__ float sm[];
    float* s_h1  = sm + S_H1_OFF;   // tf32 bits stored as float
    float* s_w2  = sm + S_W2_OFF;   // tf32 bits
    float* s_in  = sm + S_IN_OFF;
    float* s_w1  = sm + S_W1_OFF;
    float* s_red = sm + S_RED_OFF;

    const int bn  = blockIdx.x;
    const int b   = bn >> 9;
    const int n   = bn & 511;
    const int tid = threadIdx.x;

    // zero h1 (covers im2col padding + s>=200 tail) and input pad
    for (int i = tid; i < 32 * H1W; i += 256) s_h1[i] = 0.f;
    for (int i = tid; i < 2 * 208; i += 256)  s_in[i] = 0.f;

    // weights: w1 flat; w2 transposed to [r][n] tf32, row stride 72
    for (int i = tid; i < 320; i += 256) s_w1[i] = w1[i];
    for (int i = tid; i < 160 * 64; i += 256) {
        int r = i & 159;            // 160 | i? no: decompose properly below
        int nn = i / 160;
        r = i - nn * 160;
        ((uint32_t*)s_w2)[r * W2P + nn] = f2tf32(w2[nn * 160 + r]);
    }
    __syncthreads();

    // input: xf[bn][c][s] = x[b, s, 2n+c]
    const float* xb = x + (size_t)b * SEQ * (NNODES * 2) + 2 * n;
    for (int i = tid; i < 2 * SEQ; i += 256) {
        int s = i >> 1, c = i & 1;
        s_in[c * 208 + 2 + s] = xb[(size_t)s * (NNODES * 2) + c];
    }
    __syncthreads();

    // conv1: 32 oc x 200 pos -> tf32 bits at s_h1[oc][s+2]
    for (int i = tid; i < 32 * SEQ; i += 256) {
        int oc = i / SEQ, s = i - oc * SEQ;
        const float* w  = s_w1 + oc * 10;
        const float* i0 = s_in + s;
        const float* i1 = s_in + 208 + s;
        float acc = b1[oc];
#pragma unroll
        for (int k = 0; k < 5; k++)
            acc = fmaf(w[k], i0[k], fmaf(w[5 + k], i1[k], acc));
        ((uint32_t*)s_h1)[oc * H1W + 2 + s] = f2tf32(fmaxf(acc, 0.f));
    }
    __syncthreads();

    // -------- tensor-core GEMM --------
    const int warp = tid >> 5;
    const int lane = tid & 31;
    const int g    = lane >> 2;      // groupID (row within fragment)
    const int t4   = lane & 3;

    const uint32_t* h1u = (const uint32_t*)s_h1;
    const uint32_t* w2u = (const uint32_t*)s_w2;

    float c[2][8][4];
#pragma unroll
    for (int mt = 0; mt < 2; mt++)
#pragma unroll
        for (int nt = 0; nt < 8; nt++)
#pragma unroll
            for (int q = 0; q < 4; q++) c[mt][nt][q] = 0.f;

    for (int kc = 0; kc < 20; kc++) {
        const int r0 = kc * 8 + t4;
        const int r1 = r0 + 4;
        const int ic0 = r0 / 5, k0 = r0 - ic0 * 5;
        const int ic1 = r1 / 5, k1 = r1 - ic1 * 5;

        uint32_t bb0[8], bb1[8];
#pragma unroll
        for (int nt = 0; nt < 8; nt++) {
            bb0[nt] = w2u[r0 * W2P + nt * 8 + g];
            bb1[nt] = w2u[r1 * W2P + nt * 8 + g];
        }

        const int ao0 = ic0 * H1W + k0;
        const int ao1 = ic1 * H1W + k1;
#pragma unroll
        for (int mt = 0; mt < 2; mt++) {
            const int sb = (warp * 2 + mt) * 16 + g;
            uint32_t a0 = h1u[ao0 + sb];
            uint32_t a1 = h1u[ao0 + sb + 8];
            uint32_t a2 = h1u[ao1 + sb];
            uint32_t a3 = h1u[ao1 + sb + 8];
#pragma unroll
            for (int nt = 0; nt < 8; nt++)
                mma_tf32(c[mt][nt], a0, a1, a2, a3, bb0[nt], bb1[nt]);
        }
    }

    // -------- epilogue: bias + relu + sum over valid positions, reduce --------
#pragma unroll
    for (int nt = 0; nt < 8; nt++) {
        const int n0 = nt * 8 + 2 * t4;
        const float bias0 = b2[n0], bias1 = b2[n0 + 1];
        float s0 = 0.f, s1 = 0.f;
#pragma unroll
        for (int mt = 0; mt < 2; mt++) {
            const int rA = (warp * 2 + mt) * 16 + g;
            const int rB = rA + 8;
            if (rA < 200) {
                s0 += fmaxf(c[mt][nt][0] + bias0, 0.f);
                s1 += fmaxf(c[mt][nt][1] + bias1, 0.f);
            }
            if (rB < 200) {
                s0 += fmaxf(c[mt][nt][2] + bias0, 0.f);
                s1 += fmaxf(c[mt][nt][3] + bias1, 0.f);
            }
        }
#pragma unroll
        for (int off = 16; off >= 4; off >>= 1) {
            s0 += __shfl_down_sync(0xffffffffu, s0, off);
            s1 += __shfl_down_sync(0xffffffffu, s1, off);
        }
        if (lane < 4) {
            s_red[warp * 64 + nt * 8 + 2 * lane]     = s0;
            s_red[warp * 64 + nt * 8 + 2 * lane + 1] = s1;
        }
    }
    __syncthreads();

    if (tid < 64) {
        float t = 0.f;
#pragma unroll
        for (int w = 0; w < 8; w++) t += s_red[w * 64 + tid];
        h0[(size_t)bn * HID + tid] = t * (1.f / 200.f);
    }
}

// ---------------- Stage B: Wh = h @ W ; f1 = Wh@a[:64] ; f2 = Wh@a[64:] ----
__global__ void __launch_bounds__(256)
gat_pre_kernel(const float* __restrict__ h, const float* __restrict__ W,
               const float* __restrict__ a,
               float* __restrict__ Wh, float* __restrict__ f1, float* __restrict__ f2)
{
    __shared__ float sW[64 * 64];
    __shared__ float sh[16 * 64];
    __shared__ float s1[8][4], s2[8][4];

    const int tid  = threadIdx.x;
    const int row0 = blockIdx.x * 16;

    for (int i = tid; i < 64 * 64; i += 256) sW[i] = W[i];
    for (int i = tid; i < 16 * 64; i += 256) sh[i] = h[(size_t)row0 * 64 + i];
    __syncthreads();

    const int rg = tid >> 6;
    const int d  = tid & 63;
    float acc[4] = {0.f, 0.f, 0.f, 0.f};
#pragma unroll 8
    for (int k = 0; k < 64; k++) {
        float w = sW[k * 64 + d];
#pragma unroll
        for (int j = 0; j < 4; j++)
            acc[j] = fmaf(sh[(rg * 4 + j) * 64 + k], w, acc[j]);
    }
    const float a1v = a[d], a2v = a[64 + d];
    float v1[4], v2[4];
#pragma unroll
    for (int j = 0; j < 4; j++) {
        Wh[(size_t)(row0 + rg * 4 + j) * 64 + d] = acc[j];
        v1[j] = acc[j] * a1v;
        v2[j] = acc[j] * a2v;
    }
#pragma unroll
    for (int o = 16; o; o >>= 1)
#pragma unroll
        for (int j = 0; j < 4; j++) {
            v1[j] += __shfl_down_sync(0xffffffffu, v1[j], o);
            v2[j] += __shfl_down_sync(0xffffffffu, v2[j], o);
        }
    const int w = tid >> 5;
    if ((tid & 31) == 0)
#pragma unroll
        for (int j = 0; j < 4; j++) { s1[w][j] = v1[j]; s2[w][j] = v2[j]; }
    __syncthreads();
    if (tid < 16) {
        int g = tid >> 2, j = tid & 3;
        f1[row0 + g * 4 + j] = s1[2 * g][j] + s1[2 * g + 1][j];
        f2[row0 + g * 4 + j] = s2[2 * g][j] + s2[2 * g + 1][j];
    }
}

// ---------------- Stage C: attention, 8 rows per block, j-tiled Wh ----------
__global__ void __launch_bounds__(256)
gat_att_kernel(const float* __restrict__ Wh, const float* __restrict__ f1,
               const float* __restrict__ f2, const int* __restrict__ adj,
               float* __restrict__ out, int do_relu)
{
    __shared__ float sp[8][512];
    __shared__ float sWh[64][65];
    __shared__ float ssum[8];

    const int blk = blockIdx.x;
    const int b   = blk >> 6;
    const int i0  = (blk & 63) * 8;
    const int tid = threadIdx.x;
    const int w   = tid >> 5;
    const int ln  = tid & 31;

    {
        const int i  = i0 + w;
        const int bi = b * NNODES + i;
        const float f1i = f1[bi];
        const float* f2b = f2 + b * NNODES;
        const int* adjrow = adj + (size_t)i * NNODES;

        float ev[16];
        float lmax = -3.4e38f;
#pragma unroll
        for (int t = 0; t < 16; t++) {
            int j = ln + t * 32;
            float e = f1i + f2b[j];
            e = (e > 0.f) ? e : ALPHA * e;
            e = (adjrow[j] > 0) ? e : NEGBIG;
            ev[t] = e;
            lmax = fmaxf(lmax, e);
        }
#pragma unroll
        for (int o = 16; o; o >>= 1)
            lmax = fmaxf(lmax, __shfl_xor_sync(0xffffffffu, lmax, o));
        float lsum = 0.f;
#pragma unroll
        for (int t = 0; t < 16; t++) {
            float p = expf(ev[t] - lmax);
            sp[w][ln + t * 32] = p;
            lsum += p;
        }
#pragma unroll
        for (int o = 16; o; o >>= 1)
            lsum += __shfl_xor_sync(0xffffffffu, lsum, o);
        if (ln == 0) ssum[w] = lsum;
    }
    __syncthreads();

    const int g = tid >> 6;
    const int d = tid & 63;
    const float* Whb = Wh + (size_t)b * NNODES * HID;
    float acc0 = 0.f, acc1 = 0.f;

    for (int jt = 0; jt < 8; jt++) {
#pragma unroll
        for (int t = 0; t < 16; t++) {
            int idx = tid + t * 256;
            int j = idx >> 6, dd = idx & 63;
            sWh[j][dd] = Whb[(size_t)(jt * 64 + j) * 64 + dd];
        }
        __syncthreads();
        const float* p0 = &sp[2 * g][jt * 64];
        const float* p1 = &sp[2 * g + 1][jt * 64];
#pragma unroll 8
        for (int j = 0; j < 64; j++) {
            float wv = sWh[j][d];
            acc0 = fmaf(p0[j], wv, acc0);
            acc1 = fmaf(p1[j], wv, acc1);
        }
        __syncthreads();
    }

    {
        float v0 = acc0 / ssum[2 * g];
        float v1 = acc1 / ssum[2 * g + 1];
        if (do_relu) { v0 = fmaxf(v0, 0.f); v1 = fmaxf(v1, 0.f); }
        out[(size_t)(b * NNODES + i0 + 2 * g) * HID + d]     = v0;
        out[(size_t)(b * NNODES + i0 + 2 * g + 1) * HID + d] = v1;
    }
}

// ---------------- Stage D: edge gather + MLP + sigmoid ----------------
__global__ void __launch_bounds__(64)
edge_mlp_kernel(const float* __restrict__ h, const int* __restrict__ eidx,
                const float* __restrict__ fc1w, const float* __restrict__ fc1b,
                const float* __restrict__ fc2w, const float* __restrict__ fc2b,
                float* __restrict__ out)
{
    __shared__ float she[128];
    __shared__ float sr[2];

    const int e   = blockIdx.x;
    const int b   = blockIdx.y;
    const int tid = threadIdx.x;

    const int i1 = eidx[2 * e];
    const int i2 = eidx[2 * e + 1];
    she[tid]      = h[((size_t)b * NNODES + i1) * HID + tid];
    she[64 + tid] = h[((size_t)b * NNODES + i2) * HID + tid];
    __syncthreads();

    float acc = fc1b[tid];
#pragma unroll 8
    for (int k = 0; k < 128; k++)
        acc = fmaf(she[k], fc1w[(size_t)k * 64 + tid], acc);
    acc = fmaxf(acc, 0.f);

    float v = acc * fc2w[tid];
#pragma unroll
    for (int o = 16; o; o >>= 1)
        v += __shfl_down_sync(0xffffffffu, v, o);
    if ((tid & 31) == 0) sr[tid >> 5] = v;
    __syncthreads();
    if (tid == 0) {
        float z = sr[0] + sr[1] + fc2b[0];
        out[(size_t)b * NEDGES + e] = 1.f / (1.f + expf(-z));
    }
}

// ---------------- launch ----------------
extern "C" void kernel_launch(void* const* d_in, const int* in_sizes, int n_in,
                              void* d_out, int out_size)
{
    const float* x    = (const float*)d_in[0];
    const int*   adj  = (const int*)  d_in[1];
    const int*   eidx = (const int*)  d_in[2];
    const float* w1   = (const float*)d_in[3];
    const float* b1   = (const float*)d_in[4];
    const float* w2   = (const float*)d_in[5];
    const float* b2   = (const float*)d_in[6];
    const float* W1   = (const float*)d_in[7];
    const float* a1   = (const float*)d_in[8];
    const float* W2   = (const float*)d_in[9];
    const float* a2   = (const float*)d_in[10];
    const float* fc1w = (const float*)d_in[11];
    const float* fc1b = (const float*)d_in[12];
    const float* fc2w = (const float*)d_in[13];
    const float* fc2b = (const float*)d_in[14];
    float* out = (float*)d_out;

    float *h0, *Wh, *h1, *h2, *f1, *f2;
    cudaGetSymbolAddress((void**)&h0, g_h0);
    cudaGetSymbolAddress((void**)&Wh, g_Wh);
    cudaGetSymbolAddress((void**)&h1, g_h1);
    cudaGetSymbolAddress((void**)&h2, g_h2);
    cudaGetSymbolAddress((void**)&f1, g_f1);
    cudaGetSymbolAddress((void**)&f2, g_f2);

    cudaFuncSetAttribute(conv_fused_kernel,
                         cudaFuncAttributeMaxDynamicSharedMemorySize,
                         CONV_SMEM_BYTES);

    // Stage A: conv feature extractor (tf32 tensor-core implicit GEMM)
    conv_fused_kernel<<<BATCH * NNODES, 256, CONV_SMEM_BYTES>>>(x, w1, b1, w2, b2, h0);

    // GAT layer 1 (relu on output)
    gat_pre_kernel<<<(BATCH * NNODES) / 16, 256>>>(h0, W1, a1, Wh, f1, f2);
    gat_att_kernel<<<(BATCH * NNODES) / 8, 256>>>(Wh, f1, f2, adj, h1, 1);

    // GAT layer 2 (no relu)
    gat_pre_kernel<<<(BATCH * NNODES) / 16, 256>>>(h1, W2, a2, Wh, f1, f2);
    gat_att_kernel<<<(BATCH * NNODES) / 8, 256>>>(Wh, f1, f2, adj, h2, 0);

    // Edge MLP
    dim3 eg(NEDGES, BATCH);
    edge_mlp_kernel<<<eg, 64>>>(h2, eidx, fc1w, fc1b, fc2w, fc2b, out);
}